// round 7
// baseline (speedup 1.0000x reference)
#include <cuda_runtime.h>
#include <cuda_fp16.h>

#define WIN 11
#define PAD 5
#define TX 32
#define TY 32
#define INX 42
#define INY 42
#define IMG_H 512
#define IMG_W 512
#define NT 256

#define C1V 1.0e-4f
#define C2V 9.0e-4f
#define EPS2 1.0e-12f
#define A_CHARB 0.3f
#define A_SSIM  0.6f

// Normalized 11-tap Gaussian (sigma=1.5)
#define W0 0.00102838f
#define W1 0.00759876f
#define W2 0.03600078f
#define W3 0.10936070f
#define W4 0.21300554f
#define W5 0.26601173f

__device__ __constant__ float WTAB[11] = {W0,W1,W2,W3,W4,W5,W4,W3,W2,W1,W0};

__device__ __forceinline__ float gw(int k) {   // compile-time k -> immediate
    switch (k) {
        case 0:  return W0; case 1:  return W1; case 2:  return W2;
        case 3:  return W3; case 4:  return W4; case 5:  return W5;
        case 6:  return W4; case 7:  return W3; case 8:  return W2;
        case 9:  return W1; default: return W0;
    }
}

// runtime weight lookup for A-fragment init (zero outside the band)
__device__ __forceinline__ float wv(int r, int k) {
    int d = k - r;
    return (d >= 0 && d <= 10) ? WTAB[d] : 0.f;
}
__device__ __forceinline__ unsigned packw(int r, int k) {
    __half2 h = __floats2half2_rn(wv(r, k), wv(r, k + 1));  // low = even k
    return *(unsigned*)&h;
}

// smem: input tile (float2 x,y) + 10 fp16 H-planes (5 quantities x hi/lo), K padded to 48
struct Smem {
    float2 in[INY][43];                       // 14448 B
    __align__(16) __half h[10][48][40];       // 38400 B ; row stride 80B (20 words)
};

__device__ __forceinline__ unsigned smem_u32(const void* p) {
    return (unsigned)__cvta_generic_to_shared(p);
}

__global__ __launch_bounds__(NT, 4)
void ssim_loss_kernel(const float* __restrict__ pred,
                      const float* __restrict__ targ,
                      float* __restrict__ out) {
    extern __shared__ char raw[];
    Smem* S = reinterpret_cast<Smem*>(raw);

    const int tid = threadIdx.x;
    const int lane = tid & 31;
    const int wid = tid >> 5;
    const int tile_x = blockIdx.x * TX;
    const int tile_y = blockIdx.y * TY;
    const int plane = blockIdx.z;

    const float* __restrict__ px = pred + (size_t)plane * IMG_H * IMG_W;
    const float* __restrict__ py = targ + (size_t)plane * IMG_H * IMG_W;
    float* __restrict__ po = out + (size_t)plane * IMG_H * IMG_W;

    // ---- halo load (zero-padded) ----
    #pragma unroll 1
    for (int idx = tid; idx < INY * INX; idx += NT) {
        int r = idx / INX, cc = idx - r * INX;
        int gr = tile_y + r - PAD;
        int gc = tile_x + cc - PAD;
        float2 v = make_float2(0.f, 0.f);
        if (gr >= 0 && gr < IMG_H && gc >= 0 && gc < IMG_W) {
            size_t off = (size_t)gr * IMG_W + gc;
            v.x = px[off];
            v.y = py[off];
        }
        S->in[r][cc] = v;
    }
    // ---- zero K-padding rows 42..47 of all 10 planes (read by kc=2 chunk) ----
    #pragma unroll 1
    for (int idx = tid; idx < 10 * 6 * 20; idx += NT) {
        int pl = idx / 120, rem = idx - pl * 120;
        int rr = 42 + rem / 20, cu = rem % 20;
        ((unsigned*)&S->h[pl][rr][0])[cu] = 0u;
    }
    __syncthreads();

    // ---- H-pass: scalar fp32, immediate weights; 42 rows x 4 chunks of 8 ----
    if (tid < INY * 4) {
        const int r  = tid % INY;
        const int c0 = (tid / INY) * 8;

        float ax[8], ay[8], axx[8], ayy[8], axy[8];
        #pragma unroll
        for (int j = 0; j < 8; j++) { ax[j]=0.f; ay[j]=0.f; axx[j]=0.f; ayy[j]=0.f; axy[j]=0.f; }

        #pragma unroll
        for (int i = 0; i < 18; i++) {
            float2 v = S->in[r][c0 + i];
            float xx = v.x * v.x;
            float yy = v.y * v.y;
            float xy = v.x * v.y;
            #pragma unroll
            for (int j = 0; j < 8; j++) {
                const int k = i - j;
                if (k >= 0 && k < WIN) {
                    const float wk = gw(k);
                    ax[j]  = fmaf(wk, v.x, ax[j]);
                    ay[j]  = fmaf(wk, v.y, ay[j]);
                    axx[j] = fmaf(wk, xx,  axx[j]);
                    ayy[j] = fmaf(wk, yy,  ayy[j]);
                    axy[j] = fmaf(wk, xy,  axy[j]);
                }
            }
        }

        // emit hi/lo fp16 split per plane: 8 halves = one STS.128 each
        #define EMIT_PLANE(PL, ARR)                                              \
        {                                                                        \
            unsigned hh[4], ll[4];                                               \
            _Pragma("unroll")                                                    \
            for (int q = 0; q < 4; q++) {                                        \
                float v0 = ARR[2*q], v1 = ARR[2*q+1];                            \
                __half2 hp = __floats2half2_rn(v0, v1);                          \
                float f0 = __half2float(__low2half(hp));                         \
                float f1 = __half2float(__high2half(hp));                        \
                __half2 lp = __floats2half2_rn(v0 - f0, v1 - f1);                \
                hh[q] = *(unsigned*)&hp;                                         \
                ll[q] = *(unsigned*)&lp;                                         \
            }                                                                    \
            *(uint4*)&S->h[2*(PL)  ][r][c0] = make_uint4(hh[0],hh[1],hh[2],hh[3]); \
            *(uint4*)&S->h[2*(PL)+1][r][c0] = make_uint4(ll[0],ll[1],ll[2],ll[3]); \
        }
        EMIT_PLANE(0, ax)
        EMIT_PLANE(1, ay)
        EMIT_PLANE(2, axx)
        EMIT_PLANE(3, ayy)
        EMIT_PLANE(4, axy)
        #undef EMIT_PLANE
    }
    __syncthreads();

    // ---- V-pass via tensor cores: D[32x32] = W[32x48] * H[48x32] per plane ----
    // warp = (Mtile m in {0,1}, Ntile n in {0..3}); banded W -> 2 live K-chunks per m
    const int m = wid >> 2;
    const int n = wid & 3;
    const int lr = lane >> 2;
    const int kq = (lane & 3) * 2;

    const int kc0 = (m == 0) ? 0 : 1;

    unsigned A[2][4];
    #pragma unroll
    for (int t = 0; t < 2; t++) {
        int kb = 16 * (kc0 + t);
        A[t][0] = packw(16*m + lr,     kb + kq);
        A[t][1] = packw(16*m + lr + 8, kb + kq);
        A[t][2] = packw(16*m + lr,     kb + kq + 8);
        A[t][3] = packw(16*m + lr + 8, kb + kq + 8);
    }

    float D[5][4];
    #pragma unroll
    for (int p = 0; p < 5; p++)
        #pragma unroll
        for (int e = 0; e < 4; e++) D[p][e] = 0.f;

    const int ldrow = lane & 15;   // ldmatrix x2: lanes 0-15 supply 16 row addresses

    #pragma unroll
    for (int p = 0; p < 5; p++) {
        #pragma unroll
        for (int s = 0; s < 2; s++) {          // hi then lo
            unsigned base = smem_u32(&S->h[2*p + s][0][0]);
            #pragma unroll
            for (int t = 0; t < 2; t++) {
                unsigned addr = base + (unsigned)((16*(kc0 + t) + ldrow) * 80 + 16 * n);
                unsigned b0, b1;
                asm volatile(
                    "ldmatrix.sync.aligned.m8n8.x2.trans.shared.b16 {%0,%1}, [%2];"
                    : "=r"(b0), "=r"(b1) : "r"(addr));
                asm volatile(
                    "mma.sync.aligned.m16n8k16.row.col.f32.f16.f16.f32 "
                    "{%0,%1,%2,%3}, {%4,%5,%6,%7}, {%8,%9}, {%0,%1,%2,%3};"
                    : "+f"(D[p][0]), "+f"(D[p][1]), "+f"(D[p][2]), "+f"(D[p][3])
                    : "r"(A[t][0]), "r"(A[t][1]), "r"(A[t][2]), "r"(A[t][3]),
                      "r"(b0), "r"(b1));
            }
        }
    }

    // ---- combine + store; D frag: e0=(lr,cq) e1=(lr,cq+1) e2=(lr+8,cq) e3=(lr+8,cq+1)
    #pragma unroll
    for (int hf = 0; hf < 2; hf++) {
        const int e0 = hf * 2;
        const int r_out = 16*m + lr + 8*hf;
        const int c_out = 8*n + kq;

        float2 res;
        #pragma unroll
        for (int u = 0; u < 2; u++) {
            float mu_x = D[0][e0+u];
            float mu_y = D[1][e0+u];
            float exx  = D[2][e0+u];
            float eyy  = D[3][e0+u];
            float exy  = D[4][e0+u];

            float mxy = mu_x * mu_y;
            float s2x = exx - mu_x * mu_x;
            float s2y = eyy - mu_y * mu_y;
            float sxy = exy - mxy;

            float A1 = 2.f * mxy + C1V;
            float A2 = 2.f * sxy + C2V;
            float B1 = mu_x * mu_x + mu_y * mu_y + C1V;
            float B2 = s2x + s2y + C2V;
            float ssim = __fdividef(A1, B1) * __fdividef(A2, B2);

            float2 v = S->in[r_out + PAD][c_out + u + PAD];
            float d = v.x - v.y;
            float charb = sqrtf(fmaf(d, d, EPS2));

            float r = A_CHARB * charb + 2.0f * (d * d) + A_SSIM * (1.f - ssim);
            if (u == 0) res.x = r; else res.y = r;
        }
        *(float2*)&po[(size_t)(tile_y + r_out) * IMG_W + (tile_x + c_out)] = res;
    }
}

extern "C" void kernel_launch(void* const* d_in, const int* in_sizes, int n_in,
                              void* d_out, int out_size) {
    const float* pred = (const float*)d_in[0];
    const float* targ = (const float*)d_in[1];
    float* out = (float*)d_out;

    int planes = in_sizes[0] / (IMG_H * IMG_W);   // 48

    static bool attr_set = false;
    if (!attr_set) {
        cudaFuncSetAttribute(ssim_loss_kernel,
                             cudaFuncAttributeMaxDynamicSharedMemorySize,
                             (int)sizeof(Smem));
        attr_set = true;
    }

    dim3 grid(IMG_W / TX, IMG_H / TY, planes);
    ssim_loss_kernel<<<grid, NT, sizeof(Smem)>>>(pred, targ, out);
}

// round 9
// speedup vs baseline: 1.3110x; 1.3110x over previous
#include <cuda_runtime.h>

#define WIN 11
#define PAD 5
#define TX 32
#define TY 32
#define INX 42
#define INY 42
#define IMG_H 512
#define IMG_W 512
#define NT 256

#define C1V 1.0e-4f
#define C2V 9.0e-4f
#define EPS2 1.0e-12f
#define A_CHARB 0.3f
#define A_SSIM  0.6f

// Normalized 11-tap Gaussian (sigma=1.5), double-precision derived.
#define W0 0.00102838f
#define W1 0.00759876f
#define W2 0.03600078f
#define W3 0.10936070f
#define W4 0.21300554f
#define W5 0.26601173f

__device__ __forceinline__ float gw(int k) {   // compile-time k -> FFMA immediate
    switch (k) {
        case 0:  return W0; case 1:  return W1; case 2:  return W2;
        case 3:  return W3; case 4:  return W4; case 5:  return W5;
        case 6:  return W4; case 7:  return W3; case 8:  return W2;
        case 9:  return W1; default: return W0;
    }
}

__global__ __launch_bounds__(NT, 5)
void ssim_loss_kernel(const float* __restrict__ pred,
                      const float* __restrict__ targ,
                      float* __restrict__ out) {
    __shared__ float2 s_in[INY][47];   // (x,y) interleaved; padded so H window over-read stays in-bounds
    __shared__ float4 s_h4[INY][33];   // (hx, hy, hxx, hyy)
    __shared__ float  s_h1[INY][33];   // hxy

    const int tid = threadIdx.x;
    const int tile_x = blockIdx.x * TX;
    const int tile_y = blockIdx.y * TY;
    const int plane = blockIdx.z;

    const float* __restrict__ px = pred + (size_t)plane * IMG_H * IMG_W;
    const float* __restrict__ py = targ + (size_t)plane * IMG_H * IMG_W;
    float* __restrict__ po = out + (size_t)plane * IMG_H * IMG_W;

    // ---- halo load, zero-padded (matches conv zero padding); also zero pad cols 42..46 ----
    #pragma unroll 1
    for (int idx = tid; idx < INY * 47; idx += NT) {
        int r = idx / 47, cc = idx - r * 47;
        int gr = tile_y + r - PAD;
        int gc = tile_x + cc - PAD;
        float2 v = make_float2(0.f, 0.f);
        if (cc < INX && gr >= 0 && gr < IMG_H && gc >= 0 && gc < IMG_W) {
            size_t off = (size_t)gr * IMG_W + gc;
            v.x = px[off];
            v.y = py[off];
        }
        s_in[r][cc] = v;
    }
    __syncthreads();

    // ---- H-pass: 42 rows x 7 chunks... use 6-col chunks: 42*6=252 units, one per thread ----
    if (tid < INY * 6) {
        const int r  = tid % INY;
        const int c0 = (tid / INY) * 6;          // 0,6,12,18,24,30

        float ax[6], ay[6], axx[6], ayy[6], axy[6];
        #pragma unroll
        for (int j = 0; j < 6; j++) { ax[j]=0.f; ay[j]=0.f; axx[j]=0.f; ayy[j]=0.f; axy[j]=0.f; }

        #pragma unroll
        for (int i = 0; i < 16; i++) {           // 6-1+11 = 16 window inputs
            float2 v = s_in[r][c0 + i];
            float xx = v.x * v.x;
            float yy = v.y * v.y;
            float xy = v.x * v.y;
            #pragma unroll
            for (int j = 0; j < 6; j++) {
                const int k = i - j;
                if (k >= 0 && k < WIN) {
                    const float wk = gw(k);
                    ax[j]  = fmaf(wk, v.x, ax[j]);
                    ay[j]  = fmaf(wk, v.y, ay[j]);
                    axx[j] = fmaf(wk, xx,  axx[j]);
                    ayy[j] = fmaf(wk, yy,  ayy[j]);
                    axy[j] = fmaf(wk, xy,  axy[j]);
                }
            }
        }
        #pragma unroll
        for (int j = 0; j < 6; j++) {
            if (c0 + j < TX) {                   // last chunk covers 30..35, keep 30,31
                s_h4[r][c0 + j] = make_float4(ax[j], ay[j], axx[j], ayy[j]);
                s_h1[r][c0 + j] = axy[j];
            }
        }
    }
    __syncthreads();

    // ---- V-pass: each thread owns 4 output rows of one column ----
    const int c  = tid & (TX - 1);
    const int r0 = (tid >> 5) * 4;               // 0,4,...,28

    float ax[4], ay[4], axx[4], ayy[4], axy[4];
    #pragma unroll
    for (int j = 0; j < 4; j++) { ax[j]=0.f; ay[j]=0.f; axx[j]=0.f; ayy[j]=0.f; axy[j]=0.f; }

    #pragma unroll
    for (int i = 0; i < WIN + 3; i++) {          // rows r0 .. r0+13
        float4 h = s_h4[r0 + i][c];
        float hxy = s_h1[r0 + i][c];
        #pragma unroll
        for (int j = 0; j < 4; j++) {
            const int k = i - j;
            if (k >= 0 && k < WIN) {
                const float wk = gw(k);
                ax[j]  = fmaf(wk, h.x, ax[j]);
                ay[j]  = fmaf(wk, h.y, ay[j]);
                axx[j] = fmaf(wk, h.z, axx[j]);
                ayy[j] = fmaf(wk, h.w, ayy[j]);
                axy[j] = fmaf(wk, hxy, axy[j]);
            }
        }
    }

    // ---- elementwise combine + store (single division) ----
    #pragma unroll
    for (int j = 0; j < 4; j++) {
        float mu_x = ax[j];
        float mu_y = ay[j];

        float mxy = mu_x * mu_y;
        float s2x = axx[j] - mu_x * mu_x;
        float s2y = ayy[j] - mu_y * mu_y;
        float sxy = axy[j] - mxy;

        float A1 = 2.f * mxy + C1V;
        float A2 = 2.f * sxy + C2V;
        float B1 = mu_x * mu_x + mu_y * mu_y + C1V;
        float B2 = s2x + s2y + C2V;
        float ssim = __fdividef(A1 * A2, B1 * B2);

        float2 v = s_in[r0 + j + PAD][c + PAD];
        float d = v.x - v.y;
        float charb = sqrtf(fmaf(d, d, EPS2));

        float res = A_CHARB * charb + 2.0f * (d * d) + A_SSIM * (1.f - ssim);

        po[(size_t)(tile_y + r0 + j) * IMG_W + (tile_x + c)] = res;
    }
}

extern "C" void kernel_launch(void* const* d_in, const int* in_sizes, int n_in,
                              void* d_out, int out_size) {
    const float* pred = (const float*)d_in[0];
    const float* targ = (const float*)d_in[1];
    float* out = (float*)d_out;

    int planes = in_sizes[0] / (IMG_H * IMG_W);   // 48

    dim3 grid(IMG_W / TX, IMG_H / TY, planes);
    ssim_loss_kernel<<<grid, NT>>>(pred, targ, out);
}

// round 10
// speedup vs baseline: 1.6871x; 1.2869x over previous
#include <cuda_runtime.h>

#define WIN 11
#define PAD 5
#define TX 32
#define TY 32
#define INX 42
#define INY 42
#define IMG_H 512
#define IMG_W 512
#define NT 256

#define C1V 1.0e-4f
#define C2V 9.0e-4f
#define EPS2 1.0e-12f
#define A_CHARB 0.3f
#define A_SSIM  0.6f

// Normalized 11-tap Gaussian (sigma=1.5), double-precision derived.
#define W0 0.00102838f
#define W1 0.00759876f
#define W2 0.03600078f
#define W3 0.10936070f
#define W4 0.21300554f
#define W5 0.26601173f

__device__ __forceinline__ float gw(int k) {   // compile-time k -> FFMA immediate
    switch (k) {
        case 0:  return W0; case 1:  return W1; case 2:  return W2;
        case 3:  return W3; case 4:  return W4; case 5:  return W5;
        case 6:  return W4; case 7:  return W3; case 8:  return W2;
        case 9:  return W1; default: return W0;
    }
}

__global__ __launch_bounds__(NT, 5)
void ssim_loss_kernel(const float* __restrict__ pred,
                      const float* __restrict__ targ,
                      float* __restrict__ out) {
    __shared__ float2 s_in[INY][47];   // (x,y); cols 42..46 zero pad for window over-read
    __shared__ float4 s_h4[INY][36];   // (hx, hy, hss, hxy); 36 cols so tail chunk stores unguarded

    const int tid = threadIdx.x;
    const int tile_x = blockIdx.x * TX;
    const int tile_y = blockIdx.y * TY;
    const int plane = blockIdx.z;

    const float* __restrict__ px = pred + (size_t)plane * IMG_H * IMG_W;
    const float* __restrict__ py = targ + (size_t)plane * IMG_H * IMG_W;
    float* __restrict__ po = out + (size_t)plane * IMG_H * IMG_W;

    // ---- halo load, zero-padded; incremental (r,cc) to avoid per-iter div ----
    {
        int r = tid / 47;
        int cc = tid - r * 47;
        #pragma unroll
        for (int it = 0; it < 8; it++) {          // 8*256 = 2048 >= 42*47 = 1974
            if (it * NT + tid < INY * 47) {
                int gr = tile_y + r - PAD;
                int gc = tile_x + cc - PAD;
                float2 v = make_float2(0.f, 0.f);
                if (cc < INX && gr >= 0 && gr < IMG_H && gc >= 0 && gc < IMG_W) {
                    size_t off = (size_t)gr * IMG_W + gc;
                    v.x = px[off];
                    v.y = py[off];
                }
                s_in[r][cc] = v;
            }
            // advance by 256 = 5*47 + 21
            r += 5; cc += 21;
            if (cc >= 47) { cc -= 47; r += 1; }
        }
    }
    __syncthreads();

    // ---- H-pass: 42 rows x 6-col chunks = 252 units, one per thread ----
    if (tid < INY * 6) {
        const int r  = tid % INY;
        const int c0 = (tid / INY) * 6;          // 0,6,...,30

        float ax[6], ay[6], ass[6], axy[6];
        #pragma unroll
        for (int j = 0; j < 6; j++) { ax[j]=0.f; ay[j]=0.f; ass[j]=0.f; axy[j]=0.f; }

        #pragma unroll
        for (int i = 0; i < 16; i++) {           // 6-1+11 = 16 window inputs
            float2 v = s_in[r][c0 + i];
            float ss = v.x * v.x;
            ss = fmaf(v.y, v.y, ss);             // x^2 + y^2 as one plane
            float xy = v.x * v.y;
            #pragma unroll
            for (int j = 0; j < 6; j++) {
                const int k = i - j;
                if (k >= 0 && k < WIN) {
                    const float wk = gw(k);
                    ax[j]  = fmaf(wk, v.x, ax[j]);
                    ay[j]  = fmaf(wk, v.y, ay[j]);
                    ass[j] = fmaf(wk, ss,  ass[j]);
                    axy[j] = fmaf(wk, xy,  axy[j]);
                }
            }
        }
        #pragma unroll
        for (int j = 0; j < 6; j++)
            s_h4[r][c0 + j] = make_float4(ax[j], ay[j], ass[j], axy[j]);
    }
    __syncthreads();

    // ---- V-pass: each thread owns 4 output rows of one column ----
    const int c  = tid & (TX - 1);
    const int r0 = (tid >> 5) * 4;               // 0,4,...,28

    float ax[4], ay[4], ass[4], axy[4];
    #pragma unroll
    for (int j = 0; j < 4; j++) { ax[j]=0.f; ay[j]=0.f; ass[j]=0.f; axy[j]=0.f; }

    #pragma unroll
    for (int i = 0; i < WIN + 3; i++) {          // rows r0 .. r0+13
        float4 h = s_h4[r0 + i][c];
        #pragma unroll
        for (int j = 0; j < 4; j++) {
            const int k = i - j;
            if (k >= 0 && k < WIN) {
                const float wk = gw(k);
                ax[j]  = fmaf(wk, h.x, ax[j]);
                ay[j]  = fmaf(wk, h.y, ay[j]);
                ass[j] = fmaf(wk, h.z, ass[j]);
                axy[j] = fmaf(wk, h.w, axy[j]);
            }
        }
    }

    // ---- elementwise combine + store ----
    #pragma unroll
    for (int j = 0; j < 4; j++) {
        float mu_x = ax[j];
        float mu_y = ay[j];

        float mxy = mu_x * mu_y;
        float t   = mu_x * mu_x + mu_y * mu_y;   // mu_x^2 + mu_y^2
        float sxy = axy[j] - mxy;

        float A1 = 2.f * mxy + C1V;
        float A2 = 2.f * sxy + C2V;
        float B1 = t + C1V;
        float B2 = ass[j] - t + C2V;             // (s2x + s2y) + C2
        float ssim = __fdividef(A1 * A2, B1 * B2);

        float2 v = s_in[r0 + j + PAD][c + PAD];
        float d = v.x - v.y;
        float charb = sqrtf(fmaf(d, d, EPS2));

        float res = A_CHARB * charb + 2.0f * (d * d) + A_SSIM * (1.f - ssim);

        po[(size_t)(tile_y + r0 + j) * IMG_W + (tile_x + c)] = res;
    }
}

extern "C" void kernel_launch(void* const* d_in, const int* in_sizes, int n_in,
                              void* d_out, int out_size) {
    const float* pred = (const float*)d_in[0];
    const float* targ = (const float*)d_in[1];
    float* out = (float*)d_out;

    int planes = in_sizes[0] / (IMG_H * IMG_W);   // 48

    dim3 grid(IMG_W / TX, IMG_H / TY, planes);
    ssim_loss_kernel<<<grid, NT>>>(pred, targ, out);
}

// round 11
// speedup vs baseline: 1.6912x; 1.0024x over previous
#include <cuda_runtime.h>

#define WIN 11
#define PAD 5
#define TX 32
#define TY 32
#define INX 42
#define INY 42
#define IMG_H 512
#define IMG_W 512
#define NT 256

#define C1V 1.0e-4f
#define C2V 9.0e-4f
#define EPS2 1.0e-12f
#define A_CHARB 0.3f
#define A_SSIM  0.6f

// Normalized 11-tap Gaussian (sigma=1.5), double-precision derived.
#define W0 0.00102838f
#define W1 0.00759876f
#define W2 0.03600078f
#define W3 0.10936070f
#define W4 0.21300554f
#define W5 0.26601173f

typedef unsigned long long u64;

__device__ __forceinline__ float gw(int k) {   // compile-time k -> FFMA immediate
    switch (k) {
        case 0:  return W0; case 1:  return W1; case 2:  return W2;
        case 3:  return W3; case 4:  return W4; case 5:  return W5;
        case 6:  return W4; case 7:  return W3; case 8:  return W2;
        case 9:  return W1; default: return W0;
    }
}

__device__ __forceinline__ u64 gwp(int k) {    // packed (w,w) compile-time constant
    unsigned u = __float_as_uint(gw(k));
    return ((u64)u << 32) | (u64)u;
}

__device__ __forceinline__ void fma2(u64& acc, u64 a, u64 b) {
    asm("fma.rn.f32x2 %0, %1, %2, %0;" : "+l"(acc) : "l"(a), "l"(b));
}

__device__ __forceinline__ float2 unpack2(u64 v) {
    float2 t;
    asm("mov.b64 {%0, %1}, %2;" : "=f"(t.x), "=f"(t.y) : "l"(v));
    return t;
}

struct __align__(16) U64x2 { u64 a, b; };      // one LDS.128 -> two f32x2 operands

__global__ __launch_bounds__(NT, 5)
void ssim_loss_kernel(const float* __restrict__ pred,
                      const float* __restrict__ targ,
                      float* __restrict__ out) {
    __shared__ float2 s_in[INY][47];                 // (x,y); cols 42..46 zero pad
    __shared__ __align__(16) float4 s_h4[INY][36];   // (hx, hy, hss, hxy)

    const int tid = threadIdx.x;
    const int tile_x = blockIdx.x * TX;
    const int tile_y = blockIdx.y * TY;
    const int plane = blockIdx.z;

    const float* __restrict__ px = pred + (size_t)plane * IMG_H * IMG_W;
    const float* __restrict__ py = targ + (size_t)plane * IMG_H * IMG_W;
    float* __restrict__ po = out + (size_t)plane * IMG_H * IMG_W;

    // ---- pad-zero cols 42..46 (H window over-read region) ----
    if (tid < INY * 5) {
        int r = tid / 5, c = 42 + tid % 5;
        s_in[r][c] = make_float2(0.f, 0.f);
    }

    // ---- halo load via aligned float4: 42 rows x 12 float4-units (48 cols from tile_x-8) ----
    {
        const int g0 = tile_x - 8;                   // 16B-aligned (tile_x % 32 == 0)
        #pragma unroll
        for (int rd = 0; rd < 2; rd++) {
            int unit = rd * NT + tid;
            if (unit < INY * 12) {
                int r = unit / 12, c12 = unit - r * 12;
                int gr = tile_y + r - PAD;
                int gc0 = g0 + 4 * c12;
                float4 vx = make_float4(0.f, 0.f, 0.f, 0.f);
                float4 vy = vx;
                if (gr >= 0 && gr < IMG_H && gc0 >= 0 && gc0 < IMG_W) {
                    size_t off = ((size_t)gr * IMG_W + gc0) >> 2;
                    vx = ((const float4*)px)[off];
                    vy = ((const float4*)py)[off];
                }
                int l0 = 4 * c12 - 3;                // local col of vx.x
                float xs[4] = {vx.x, vx.y, vx.z, vx.w};
                float ys[4] = {vy.x, vy.y, vy.z, vy.w};
                #pragma unroll
                for (int q = 0; q < 4; q++) {
                    int l = l0 + q;
                    if (l >= 0 && l < INX)
                        s_in[r][l] = make_float2(xs[q], ys[q]);
                }
            }
        }
    }
    __syncthreads();

    // ---- H-pass: 42 rows x 6-col chunks = 252 units, one per thread (scalar, imm weights) ----
    if (tid < INY * 6) {
        const int r  = tid % INY;
        const int c0 = (tid / INY) * 6;              // 0,6,...,30

        float ax[6], ay[6], ass[6], axy[6];
        #pragma unroll
        for (int j = 0; j < 6; j++) { ax[j]=0.f; ay[j]=0.f; ass[j]=0.f; axy[j]=0.f; }

        #pragma unroll
        for (int i = 0; i < 16; i++) {
            float2 v = s_in[r][c0 + i];
            float ss = fmaf(v.y, v.y, v.x * v.x);
            float xy = v.x * v.y;
            #pragma unroll
            for (int j = 0; j < 6; j++) {
                const int k = i - j;
                if (k >= 0 && k < WIN) {
                    const float wk = gw(k);
                    ax[j]  = fmaf(wk, v.x, ax[j]);
                    ay[j]  = fmaf(wk, v.y, ay[j]);
                    ass[j] = fmaf(wk, ss,  ass[j]);
                    axy[j] = fmaf(wk, xy,  axy[j]);
                }
            }
        }
        #pragma unroll
        for (int j = 0; j < 6; j++)
            s_h4[r][c0 + j] = make_float4(ax[j], ay[j], ass[j], axy[j]);
    }
    __syncthreads();

    // ---- V-pass: f32x2 on register pairs straight out of LDS.128 ----
    const int c  = tid & (TX - 1);
    const int r0 = (tid >> 5) * 4;                   // 0,4,...,28

    u64 a01[4], a23[4];
    #pragma unroll
    for (int j = 0; j < 4; j++) { a01[j] = 0ull; a23[j] = 0ull; }

    const U64x2* __restrict__ hp = reinterpret_cast<const U64x2*>(&s_h4[0][0]);

    #pragma unroll
    for (int i = 0; i < WIN + 3; i++) {              // rows r0 .. r0+13
        U64x2 h = hp[(r0 + i) * 36 + c];             // h.a=(hx,hy), h.b=(hss,hxy)
        #pragma unroll
        for (int j = 0; j < 4; j++) {
            const int k = i - j;
            if (k >= 0 && k < WIN) {
                fma2(a01[j], h.a, gwp(k));
                fma2(a23[j], h.b, gwp(k));
            }
        }
    }

    // ---- elementwise combine + store ----
    #pragma unroll
    for (int j = 0; j < 4; j++) {
        float2 mu = unpack2(a01[j]);
        float2 e  = unpack2(a23[j]);
        float mu_x = mu.x, mu_y = mu.y;

        float mxy = mu_x * mu_y;
        float t   = mu_x * mu_x + mu_y * mu_y;
        float sxy = e.y - mxy;

        float A1 = 2.f * mxy + C1V;
        float A2 = 2.f * sxy + C2V;
        float B1 = t + C1V;
        float B2 = e.x - t + C2V;
        float ssim = __fdividef(A1 * A2, B1 * B2);

        float2 v = s_in[r0 + j + PAD][c + PAD];
        float d = v.x - v.y;
        float charb = sqrtf(fmaf(d, d, EPS2));

        float res = A_CHARB * charb + 2.0f * (d * d) + A_SSIM * (1.f - ssim);

        po[(size_t)(tile_y + r0 + j) * IMG_W + (tile_x + c)] = res;
    }
}

extern "C" void kernel_launch(void* const* d_in, const int* in_sizes, int n_in,
                              void* d_out, int out_size) {
    const float* pred = (const float*)d_in[0];
    const float* targ = (const float*)d_in[1];
    float* out = (float*)d_out;

    int planes = in_sizes[0] / (IMG_H * IMG_W);   // 48

    dim3 grid(IMG_W / TX, IMG_H / TY, planes);
    ssim_loss_kernel<<<grid, NT>>>(pred, targ, out);
}

// round 12
// speedup vs baseline: 1.9529x; 1.1548x over previous
#include <cuda_runtime.h>

#define WIN 11
#define PAD 5
#define TX 32
#define TY 32
#define INX 42
#define INY 42
#define IMG_H 512
#define IMG_W 512
#define NT 256

#define C1V 1.0e-4f
#define C2V 9.0e-4f
#define EPS2 1.0e-12f
#define A_CHARB 0.3f
#define A_SSIM  0.6f

// Normalized 11-tap Gaussian (sigma=1.5), double-precision derived.
#define W0 0.00102838f
#define W1 0.00759876f
#define W2 0.03600078f
#define W3 0.10936070f
#define W4 0.21300554f
#define W5 0.26601173f

// s_h4 row stride in float4 units — MUST be odd: H-pass STS.128 walks rows
// within a warp, quad-bank = (HSTRIDE*r + c) mod 8; odd stride => conflict-free.
#define HSTRIDE 37

typedef unsigned long long u64;

__device__ __forceinline__ float gw(int k) {   // compile-time k -> FFMA immediate
    switch (k) {
        case 0:  return W0; case 1:  return W1; case 2:  return W2;
        case 3:  return W3; case 4:  return W4; case 5:  return W5;
        case 6:  return W4; case 7:  return W3; case 8:  return W2;
        case 9:  return W1; default: return W0;
    }
}

__device__ __forceinline__ u64 gwp(int k) {    // packed (w,w) compile-time constant
    unsigned u = __float_as_uint(gw(k));
    return ((u64)u << 32) | (u64)u;
}

__device__ __forceinline__ void fma2(u64& acc, u64 a, u64 b) {
    asm("fma.rn.f32x2 %0, %1, %2, %0;" : "+l"(acc) : "l"(a), "l"(b));
}

__device__ __forceinline__ float2 unpack2(u64 v) {
    float2 t;
    asm("mov.b64 {%0, %1}, %2;" : "=f"(t.x), "=f"(t.y) : "l"(v));
    return t;
}

struct __align__(16) U64x2 { u64 a, b; };      // one LDS.128 -> two f32x2 operands

__global__ __launch_bounds__(NT, 5)
void ssim_loss_kernel(const float* __restrict__ pred,
                      const float* __restrict__ targ,
                      float* __restrict__ out) {
    __shared__ float2 s_in[INY][47];                     // (x,y); cols 42..46 zero pad
    __shared__ __align__(16) float4 s_h4[INY][HSTRIDE];  // (hx, hy, hss, hxy)

    const int tid = threadIdx.x;
    const int tile_x = blockIdx.x * TX;
    const int tile_y = blockIdx.y * TY;
    const int plane = blockIdx.z;

    const float* __restrict__ px = pred + (size_t)plane * IMG_H * IMG_W;
    const float* __restrict__ py = targ + (size_t)plane * IMG_H * IMG_W;
    float* __restrict__ po = out + (size_t)plane * IMG_H * IMG_W;

    // ---- pad-zero cols 42..46 (H window over-read region) ----
    if (tid < INY * 5) {
        int r = tid / 5, c = 42 + tid % 5;
        s_in[r][c] = make_float2(0.f, 0.f);
    }

    // ---- halo load via aligned float4: 42 rows x 12 float4-units (48 cols from tile_x-8) ----
    {
        const int g0 = tile_x - 8;                   // 16B-aligned (tile_x % 32 == 0)
        #pragma unroll
        for (int rd = 0; rd < 2; rd++) {
            int unit = rd * NT + tid;
            if (unit < INY * 12) {
                int r = unit / 12, c12 = unit - r * 12;
                int gr = tile_y + r - PAD;
                int gc0 = g0 + 4 * c12;
                float4 vx = make_float4(0.f, 0.f, 0.f, 0.f);
                float4 vy = vx;
                if (gr >= 0 && gr < IMG_H && gc0 >= 0 && gc0 < IMG_W) {
                    size_t off = ((size_t)gr * IMG_W + gc0) >> 2;
                    vx = ((const float4*)px)[off];
                    vy = ((const float4*)py)[off];
                }
                int l0 = 4 * c12 - 3;                // local col of vx.x
                float xs[4] = {vx.x, vx.y, vx.z, vx.w};
                float ys[4] = {vy.x, vy.y, vy.z, vy.w};
                #pragma unroll
                for (int q = 0; q < 4; q++) {
                    int l = l0 + q;
                    if (l >= 0 && l < INX)
                        s_in[r][l] = make_float2(xs[q], ys[q]);
                }
            }
        }
    }
    __syncthreads();

    // ---- H-pass: 42 rows x 6-col chunks = 252 units, one per thread (scalar, imm weights) ----
    if (tid < INY * 6) {
        const int r  = tid % INY;
        const int c0 = (tid / INY) * 6;              // 0,6,...,30

        float ax[6], ay[6], ass[6], axy[6];
        #pragma unroll
        for (int j = 0; j < 6; j++) { ax[j]=0.f; ay[j]=0.f; ass[j]=0.f; axy[j]=0.f; }

        #pragma unroll
        for (int i = 0; i < 16; i++) {
            float2 v = s_in[r][c0 + i];
            float ss = fmaf(v.y, v.y, v.x * v.x);
            float xy = v.x * v.y;
            #pragma unroll
            for (int j = 0; j < 6; j++) {
                const int k = i - j;
                if (k >= 0 && k < WIN) {
                    const float wk = gw(k);
                    ax[j]  = fmaf(wk, v.x, ax[j]);
                    ay[j]  = fmaf(wk, v.y, ay[j]);
                    ass[j] = fmaf(wk, ss,  ass[j]);
                    axy[j] = fmaf(wk, xy,  axy[j]);
                }
            }
        }
        #pragma unroll
        for (int j = 0; j < 6; j++)
            s_h4[r][c0 + j] = make_float4(ax[j], ay[j], ass[j], axy[j]);
    }
    __syncthreads();

    // ---- V-pass: f32x2 on register pairs straight out of LDS.128 ----
    const int c  = tid & (TX - 1);
    const int r0 = (tid >> 5) * 4;                   // 0,4,...,28

    u64 a01[4], a23[4];
    #pragma unroll
    for (int j = 0; j < 4; j++) { a01[j] = 0ull; a23[j] = 0ull; }

    const U64x2* __restrict__ hp = reinterpret_cast<const U64x2*>(&s_h4[0][0]);

    #pragma unroll
    for (int i = 0; i < WIN + 3; i++) {              // rows r0 .. r0+13
        U64x2 h = hp[(r0 + i) * HSTRIDE + c];        // h.a=(hx,hy), h.b=(hss,hxy)
        #pragma unroll
        for (int j = 0; j < 4; j++) {
            const int k = i - j;
            if (k >= 0 && k < WIN) {
                fma2(a01[j], h.a, gwp(k));
                fma2(a23[j], h.b, gwp(k));
            }
        }
    }

    // ---- elementwise combine + store ----
    #pragma unroll
    for (int j = 0; j < 4; j++) {
        float2 mu = unpack2(a01[j]);
        float2 e  = unpack2(a23[j]);
        float mu_x = mu.x, mu_y = mu.y;

        float mxy = mu_x * mu_y;
        float t   = mu_x * mu_x + mu_y * mu_y;
        float sxy = e.y - mxy;

        float A1 = 2.f * mxy + C1V;
        float A2 = 2.f * sxy + C2V;
        float B1 = t + C1V;
        float B2 = e.x - t + C2V;
        float ssim = __fdividef(A1 * A2, B1 * B2);

        float2 v = s_in[r0 + j + PAD][c + PAD];
        float d = v.x - v.y;
        float charb = sqrtf(fmaf(d, d, EPS2));

        float res = A_CHARB * charb + 2.0f * (d * d) + A_SSIM * (1.f - ssim);

        po[(size_t)(tile_y + r0 + j) * IMG_W + (tile_x + c)] = res;
    }
}

extern "C" void kernel_launch(void* const* d_in, const int* in_sizes, int n_in,
                              void* d_out, int out_size) {
    const float* pred = (const float*)d_in[0];
    const float* targ = (const float*)d_in[1];
    float* out = (float*)d_out;

    int planes = in_sizes[0] / (IMG_H * IMG_W);   // 48

    dim3 grid(IMG_W / TX, IMG_H / TY, planes);
    ssim_loss_kernel<<<grid, NT>>>(pred, targ, out);
}